// round 2
// baseline (speedup 1.0000x reference)
#include <cuda_runtime.h>

// Problem constants (fixed by the dataset)
#define B_  4
#define T_  2048
#define NH_ 8
#define N_  64
#define D_  128
#define C_  128          // chunk length
#define NC_ 16           // T_/C_
#define OUT_ELEMS (B_*T_*NH_*D_)   // 8,388,608
#define ST_ELEMS  (B_*NH_*N_*D_)   // 262,144

// Scratch: per-chunk delta-state, later overwritten by exclusive prefix.
// [B*NH][NC][N][D]
__device__ float g_dS[(size_t)B_*NH_*NC_*N_*D_];

// ---------------------------------------------------------------------------
// packed f32x2 helpers (Blackwell sm_103a)
// ---------------------------------------------------------------------------
__device__ __forceinline__ void fma2(unsigned long long& d,
                                     unsigned long long a,
                                     unsigned long long b) {
    asm("fma.rn.f32x2 %0, %1, %2, %0;" : "+l"(d) : "l"(a), "l"(b));
}
__device__ __forceinline__ float hadd2(unsigned long long v) {
    float x, y;
    asm("mov.b64 {%0, %1}, %2;" : "=f"(x), "=f"(y) : "l"(v));
    return x + y;
}

// ---------------------------------------------------------------------------
// Kernel A: dS[b,h,k][n][d] = sum_c Q[b, kC+c, h, n] * V[b, kC+c, d]
// grid = B*NH*NC = 512 blocks, 256 threads.
// Both operands stored c-transposed in smem so f32x2 pairs run along c.
// ---------------------------------------------------------------------------
#define KA_SMEM ((64 + 128) * 132 * 4)

__global__ __launch_bounds__(256, 1) void kA(const float* __restrict__ Q,
                                             const float* __restrict__ V) {
    extern __shared__ float s[];
    float* Qt = s;              // [64][132]   Qt[n][c]
    float* Vt = s + 64 * 132;   // [128][132]  Vt[d][c]

    const int tid = threadIdx.x;
    const int blk = blockIdx.x;
    const int k = blk % NC_, bh = blk / NC_;
    const int b = bh / NH_, h = bh % NH_;

    const float* Qb = Q + ((size_t)(b * T_ + k * C_) * NH_ + h) * N_;
    const float* Vb = V + (size_t)(b * T_ + k * C_) * D_;

    // Load Q chunk [C_ x N_] transposed into Qt[n][c]
#pragma unroll
    for (int it = 0; it < 8; it++) {
        int idx = tid + it * 256;           // 2048 float4s
        int c = idx >> 4, n4 = idx & 15;
        float4 q = *(const float4*)(Qb + (size_t)c * NH_ * N_ + n4 * 4);
        Qt[(n4 * 4 + 0) * 132 + c] = q.x;
        Qt[(n4 * 4 + 1) * 132 + c] = q.y;
        Qt[(n4 * 4 + 2) * 132 + c] = q.z;
        Qt[(n4 * 4 + 3) * 132 + c] = q.w;
    }
    // Load V chunk [C_ x D_] transposed into Vt[d][c]
#pragma unroll
    for (int it = 0; it < 16; it++) {
        int idx = tid + it * 256;           // 4096 float4s
        int c = idx >> 5, d4 = idx & 31;
        float4 v = *(const float4*)(Vb + (size_t)c * D_ + d4 * 4);
        Vt[(d4 * 4 + 0) * 132 + c] = v.x;
        Vt[(d4 * 4 + 1) * 132 + c] = v.y;
        Vt[(d4 * 4 + 2) * 132 + c] = v.z;
        Vt[(d4 * 4 + 3) * 132 + c] = v.w;
    }
    __syncthreads();

    const int ty = tid >> 4, tx = tid & 15;
    unsigned long long acc[4][8];
#pragma unroll
    for (int i = 0; i < 4; i++)
#pragma unroll
        for (int j = 0; j < 8; j++) acc[i][j] = 0ULL;

#pragma unroll 4
    for (int cc = 0; cc < C_; cc += 4) {
        ulonglong2 a[4];
#pragma unroll
        for (int i = 0; i < 4; i++)
            a[i] = *(const ulonglong2*)&Qt[(ty + 16 * i) * 132 + cc];
#pragma unroll
        for (int j = 0; j < 8; j++) {
            ulonglong2 bb = *(const ulonglong2*)&Vt[(tx + 16 * j) * 132 + cc];
#pragma unroll
            for (int i = 0; i < 4; i++) {
                fma2(acc[i][j], a[i].x, bb.x);
                fma2(acc[i][j], a[i].y, bb.y);
            }
        }
    }

    float* outp = g_dS + (size_t)blk * (N_ * D_);
#pragma unroll
    for (int i = 0; i < 4; i++)
#pragma unroll
        for (int j = 0; j < 8; j++)
            outp[(ty + 16 * i) * D_ + (tx + 16 * j)] = hadd2(acc[i][j]);
}

// ---------------------------------------------------------------------------
// Kernel B: in-place exclusive prefix over the 16 chunks; writes new_state.
// 262144 threads, each owns one (bh, n, d) element.
// ---------------------------------------------------------------------------
__global__ void kB(const float* __restrict__ state, float* __restrict__ out_state) {
    int gid = blockIdx.x * 256 + threadIdx.x;      // < 262144
    int bh = gid >> 13;                            // / 8192
    int e  = gid & 8191;
    float* p = g_dS + (size_t)bh * NC_ * 8192 + e;
    float run = 0.f;
#pragma unroll
    for (int k = 0; k < NC_; k++) {
        float v = p[(size_t)k * 8192];
        p[(size_t)k * 8192] = run;                 // exclusive prefix
        run += v;
    }
    if (out_state) out_state[gid] = state[gid] + run;   // new_state
}

// ---------------------------------------------------------------------------
// Kernel C: per chunk:
//   scores = tril(Q_k Q_kᵀ, -1)                         (128x128)
//   out_k  = Q_k @ (state + prefix_k)  +  scores @ V_k  (128x128)
// grid = 512 blocks, 256 threads, 8x8 tile/thread, f32x2 along reduction dim.
// ---------------------------------------------------------------------------
#define KC_SMEM ((128*68 + 128*68 + 128*132 + 128*132) * 4)   // 204,800 B

__global__ __launch_bounds__(256, 1) void kC(const float* __restrict__ Q,
                                             const float* __restrict__ V,
                                             const float* __restrict__ state,
                                             float* __restrict__ out) {
    extern __shared__ float s[];
    float* Qs = s;                    // [128][68]   Qs[t][n]
    float* St = Qs + 128 * 68;        // [128][68]   St[d][n]  (state+prefix, transposed)
    float* Vt = St + 128 * 68;        // [128][132]  Vt[d][u]
    float* Sc = Vt + 128 * 132;       // [128][132]  Sc[t][u]  (masked scores)

    const int tid = threadIdx.x;
    const int blk = blockIdx.x;
    const int k = blk % NC_, bh = blk / NC_;
    const int b = bh / NH_, h = bh % NH_;

    const float* Qb  = Q + ((size_t)(b * T_ + k * C_) * NH_ + h) * N_;
    const float* Vb  = V + (size_t)(b * T_ + k * C_) * D_;
    const float* Stb = state + (size_t)bh * N_ * D_;
    const float* dSb = g_dS + (size_t)blk * (N_ * D_);

    // Qs direct [t][n]
#pragma unroll
    for (int it = 0; it < 8; it++) {
        int idx = tid + it * 256;           // 2048 float4s
        int t = idx >> 4, n4 = idx & 15;
        *(float4*)&Qs[t * 68 + n4 * 4] =
            *(const float4*)(Qb + (size_t)t * NH_ * N_ + n4 * 4);
    }
    // Vt transposed [d][u]
#pragma unroll
    for (int it = 0; it < 16; it++) {
        int idx = tid + it * 256;           // 4096 float4s
        int u = idx >> 5, d4 = idx & 31;
        float4 v = *(const float4*)(Vb + (size_t)u * D_ + d4 * 4);
        Vt[(d4 * 4 + 0) * 132 + u] = v.x;
        Vt[(d4 * 4 + 1) * 132 + u] = v.y;
        Vt[(d4 * 4 + 2) * 132 + u] = v.z;
        Vt[(d4 * 4 + 3) * 132 + u] = v.w;
    }
    // St transposed [d][n] = state + exclusive prefix
#pragma unroll
    for (int it = 0; it < 8; it++) {
        int idx = tid + it * 256;           // 2048 float4s
        int n = idx >> 5, d4 = idx & 31;
        float4 sv = *(const float4*)(Stb + (size_t)n * D_ + d4 * 4);
        float4 dv = *(const float4*)(dSb + (size_t)n * D_ + d4 * 4);
        St[(d4 * 4 + 0) * 68 + n] = sv.x + dv.x;
        St[(d4 * 4 + 1) * 68 + n] = sv.y + dv.y;
        St[(d4 * 4 + 2) * 68 + n] = sv.z + dv.z;
        St[(d4 * 4 + 3) * 68 + n] = sv.w + dv.w;
    }
    __syncthreads();

    const int ty = tid >> 4, tx = tid & 15;

    // ---- Phase 1: scores[t][u] = Q_t . Q_u, strictly-lower mask ----
    unsigned long long acc[8][8];
#pragma unroll
    for (int i = 0; i < 8; i++)
#pragma unroll
        for (int j = 0; j < 8; j++) acc[i][j] = 0ULL;

#pragma unroll 4
    for (int nn = 0; nn < N_; nn += 4) {
        ulonglong2 a[8];
#pragma unroll
        for (int i = 0; i < 8; i++)
            a[i] = *(const ulonglong2*)&Qs[(ty + 16 * i) * 68 + nn];
#pragma unroll
        for (int j = 0; j < 8; j++) {
            ulonglong2 bb = *(const ulonglong2*)&Qs[(tx + 16 * j) * 68 + nn];
#pragma unroll
            for (int i = 0; i < 8; i++) {
                fma2(acc[i][j], a[i].x, bb.x);
                fma2(acc[i][j], a[i].y, bb.y);
            }
        }
    }
#pragma unroll
    for (int i = 0; i < 8; i++) {
        int t = ty + 16 * i;
#pragma unroll
        for (int j = 0; j < 8; j++) {
            int u = tx + 16 * j;
            Sc[t * 132 + u] = (u < t) ? hadd2(acc[i][j]) : 0.f;
        }
    }
    __syncthreads();

    // ---- Phase 2: out[t][d] = Qs[t][:]@St[d][:] + Sc[t][:]@Vt[d][:] ----
#pragma unroll
    for (int i = 0; i < 8; i++)
#pragma unroll
        for (int j = 0; j < 8; j++) acc[i][j] = 0ULL;

#pragma unroll 4
    for (int nn = 0; nn < N_; nn += 4) {
        ulonglong2 a[8];
#pragma unroll
        for (int i = 0; i < 8; i++)
            a[i] = *(const ulonglong2*)&Qs[(ty + 16 * i) * 68 + nn];
#pragma unroll
        for (int j = 0; j < 8; j++) {
            ulonglong2 bb = *(const ulonglong2*)&St[(tx + 16 * j) * 68 + nn];
#pragma unroll
            for (int i = 0; i < 8; i++) {
                fma2(acc[i][j], a[i].x, bb.x);
                fma2(acc[i][j], a[i].y, bb.y);
            }
        }
    }
#pragma unroll 4
    for (int uu = 0; uu < C_; uu += 4) {
        ulonglong2 a[8];
#pragma unroll
        for (int i = 0; i < 8; i++)
            a[i] = *(const ulonglong2*)&Sc[(ty + 16 * i) * 132 + uu];
#pragma unroll
        for (int j = 0; j < 8; j++) {
            ulonglong2 bb = *(const ulonglong2*)&Vt[(tx + 16 * j) * 132 + uu];
#pragma unroll
            for (int i = 0; i < 8; i++) {
                fma2(acc[i][j], a[i].x, bb.x);
                fma2(acc[i][j], a[i].y, bb.y);
            }
        }
    }

    float* ob = out + ((size_t)(b * T_ + k * C_) * NH_ + h) * D_;
#pragma unroll
    for (int i = 0; i < 8; i++) {
        int t = ty + 16 * i;
#pragma unroll
        for (int j = 0; j < 8; j++)
            ob[(size_t)t * NH_ * D_ + (tx + 16 * j)] = hadd2(acc[i][j]);
    }
}

// ---------------------------------------------------------------------------
extern "C" void kernel_launch(void* const* d_in, const int* in_sizes, int n_in,
                              void* d_out, int out_size) {
    const float* Q     = (const float*)d_in[0];
    const float* V     = (const float*)d_in[1];
    const float* state = (const float*)d_in[2];
    float* out = (float*)d_out;

    cudaFuncSetAttribute(kA, cudaFuncAttributeMaxDynamicSharedMemorySize, KA_SMEM);
    cudaFuncSetAttribute(kC, cudaFuncAttributeMaxDynamicSharedMemorySize, KC_SMEM);

    bool write_state = (out_size >= (OUT_ELEMS + ST_ELEMS));
    float* out_state = write_state ? (out + OUT_ELEMS) : nullptr;

    kA<<<B_ * NH_ * NC_, 256, KA_SMEM>>>(Q, V);
    kB<<<ST_ELEMS / 256, 256>>>(state, out_state);
    kC<<<B_ * NH_ * NC_, 256, KC_SMEM>>>(Q, V, state, out);
}